// round 4
// baseline (speedup 1.0000x reference)
#include <cuda_runtime.h>
#include <math.h>
#include <stdint.h>

#define SN    255
#define B_    64
#define EMB   200
#define HID   300
#define NROWS (SN * B_)     // 16320
#define NC    1200          // concat cols: [iou(900) | f(300)]
#define NPAD  1216          // 19 * 64
#define KCH_E 13            // ceil(200/16)
#define KCH_U 19            // ceil(300/16)
#define NBG   152           // NPAD / 8

// ---- device scratch (no allocation in kernel_launch) ----
__device__ float g_wx[NROWS * NC];         // x-part preacts + bias, all nodes
__device__ float g_H [NROWS * HID];
__device__ float g_C [NROWS * HID];
__device__ float g_T [8192 * NC];          // per-level child GEMM out
// B matrices pre-packed in mma-fragment order:
// entry ((nbg*KCH + kch)*32 + lane) = uint4{ B[n][k+tk], B[n][k+tk+4], B[n][k+8+tk], B[n][k+12+tk] }
// with n = nbg*8 + (lane>>2), tk = lane&3, k = kch*16, tf32-converted, n-major source.
__device__ uint4 g_Bw_f[NBG * KCH_E * 32]; // [W_iou|W_f]
__device__ uint4 g_Bu_f[NBG * KCH_U * 32]; // [U_iou|U_f]
__device__ float g_bias[NC];

__device__ __forceinline__ float sigmoidf(float x) { return 1.0f / (1.0f + expf(-x)); }
__device__ __forceinline__ uint32_t f2tf(float x) {
    uint32_t u; asm("cvt.rna.tf32.f32 %0, %1;" : "=r"(u) : "f"(x)); return u;
}

// ---------------------------------------------------------------------------
// Prep: pack tf32 B matrices into fragment order + concat bias.
// ---------------------------------------------------------------------------
__global__ void prep_kernel(const float* __restrict__ W_iou, const float* __restrict__ W_f,
                            const float* __restrict__ U_iou, const float* __restrict__ U_f,
                            const float* __restrict__ b_iou, const float* __restrict__ b_f)
{
    int idx = blockIdx.x * blockDim.x + threadIdx.x;

    if (idx < NBG * KCH_E * 32) {
        int lane = idx & 31;
        int kch  = (idx >> 5) % KCH_E;
        int nbg  = idx / (32 * KCH_E);
        int n  = nbg * 8 + (lane >> 2);
        int tk = lane & 3;
        int kb = kch * 16;
        uint4 v; uint32_t* vp = (uint32_t*)&v;
        #pragma unroll
        for (int q = 0; q < 4; ++q) {
            int k = kb + tk + q * 4;
            float f = 0.0f;
            if (k < EMB && n < NC)
                f = (n < 900) ? W_iou[k * 900 + n] : W_f[k * 300 + (n - 900)];
            vp[q] = f2tf(f);
        }
        g_Bw_f[idx] = v;
    }
    if (idx < NBG * KCH_U * 32) {
        int lane = idx & 31;
        int kch  = (idx >> 5) % KCH_U;
        int nbg  = idx / (32 * KCH_U);
        int n  = nbg * 8 + (lane >> 2);
        int tk = lane & 3;
        int kb = kch * 16;
        uint4 v; uint32_t* vp = (uint32_t*)&v;
        #pragma unroll
        for (int q = 0; q < 4; ++q) {
            int k = kb + tk + q * 4;
            float f = 0.0f;
            if (k < HID && n < NC)
                f = (n < 900) ? U_iou[k * 900 + n] : U_f[k * 300 + (n - 900)];
            vp[q] = f2tf(f);
        }
        g_Bu_f[idx] = v;
    }
    if (idx < NC) g_bias[idx] = (idx < 900) ? b_iou[idx] : b_f[idx - 900];
}

// ---------------------------------------------------------------------------
// tf32 GEMM: block tile 128(M) x 64(N), BK=16, 128 threads = 4 warps stacked
// in M, each warp 32x64 (2 M-frags x 8 N-frags, m16n8k8).
// Fragment-ordered smem: A consumed via lds.128, B via lds.128 (pair covers
// both k-substeps). B comes pre-packed from global.
// MODE 0: A = embed[x[row]] (K=200) -> g_wx (+bias)
// MODE 1: A = g_H rows from node c0 (K=300) -> g_T
// ---------------------------------------------------------------------------
template<int MODE>
__global__ __launch_bounds__(128) void gemm_tf32(
    const float* __restrict__ embedTab, const int* __restrict__ xg,
    int c0, int Mrows)
{
    constexpr int KSRC = (MODE == 0) ? EMB : HID;
    constexpr int KCH  = (MODE == 0) ? KCH_E : KCH_U;

    __shared__ __align__(16) uint4 As[8][2][32];   // [mb][kb][lane] 8KB
    __shared__ __align__(16) uint4 Bs[8][32];      // [nb][lane]     4KB
    __shared__ const float* arows[128];

    const int tid     = threadIdx.x;
    const int rowBase = blockIdx.x * 128;
    const int colBase = blockIdx.y * 64;

    {
        int row = rowBase + tid;
        int rc  = (row < Mrows) ? row : (Mrows - 1);
        arows[tid] = (MODE == 0)
            ? embedTab + (size_t)xg[rc] * EMB
            : g_H + (size_t)(c0 * B_ + rc) * HID;
    }
    __syncthreads();

    const int lane = tid & 31, warp = tid >> 5;
    const int tg = lane >> 2, tk = lane & 3;
    const uint4* gBf = (MODE == 0) ? g_Bw_f : g_Bu_f;
    const int nbgBase = colBase >> 3;

    float acc[2][8][4] = {};

    for (int kch = 0; kch < KCH; ++kch) {
        const int k0 = kch * 16;

        // B fill: 256 uint4, coalesced LDG.128 -> STS.128
        #pragma unroll
        for (int i = 0; i < 2; ++i) {
            int e  = tid + i * 128;
            int nb = e >> 5, ln = e & 31;
            Bs[nb][ln] = gBf[((size_t)(nbgBase + nb) * KCH + kch) * 32 + ln];
        }
        // A fill: 512 uint4 fragment entries
        #pragma unroll
        for (int i = 0; i < 4; ++i) {
            int e   = tid + i * 128;
            int ln  = e & 31;
            int kb  = (e >> 5) & 1;
            int mb  = e >> 6;
            int tg2 = ln >> 2, tk2 = ln & 3;
            const float* r0 = arows[mb * 16 + tg2];
            const float* r1 = arows[mb * 16 + 8 + tg2];
            int k = k0 + kb * 8 + tk2;
            float v0 = 0.0f, v1 = 0.0f, v2 = 0.0f, v3 = 0.0f;
            if (k < KSRC)     { v0 = r0[k];     v1 = r1[k];     }
            if (k + 4 < KSRC) { v2 = r0[k + 4]; v3 = r1[k + 4]; }
            As[mb][kb][ln] = make_uint4(f2tf(v0), f2tf(v1), f2tf(v2), f2tf(v3));
        }
        __syncthreads();

        uint4 bq[8];
        #pragma unroll
        for (int nf = 0; nf < 8; ++nf) bq[nf] = Bs[nf][lane];

        #pragma unroll
        for (int kb = 0; kb < 2; ++kb) {
            uint4 aq[2];
            aq[0] = As[warp * 2 + 0][kb][lane];
            aq[1] = As[warp * 2 + 1][kb][lane];
            #pragma unroll
            for (int mf = 0; mf < 2; ++mf) {
                #pragma unroll
                for (int nf = 0; nf < 8; ++nf) {
                    uint32_t b0 = kb ? bq[nf].z : bq[nf].x;
                    uint32_t b1 = kb ? bq[nf].w : bq[nf].y;
                    asm("mma.sync.aligned.m16n8k8.row.col.f32.tf32.tf32.f32 "
                        "{%0,%1,%2,%3},{%4,%5,%6,%7},{%8,%9},{%0,%1,%2,%3};"
                        : "+f"(acc[mf][nf][0]), "+f"(acc[mf][nf][1]),
                          "+f"(acc[mf][nf][2]), "+f"(acc[mf][nf][3])
                        : "r"(aq[mf].x), "r"(aq[mf].y), "r"(aq[mf].z), "r"(aq[mf].w),
                          "r"(b0), "r"(b1));
                }
            }
        }
        __syncthreads();
    }

    // Epilogue: float2 stores
    float* Cout = (MODE == 0) ? g_wx : g_T;
    #pragma unroll
    for (int mf = 0; mf < 2; ++mf) {
        #pragma unroll
        for (int nf = 0; nf < 8; ++nf) {
            int row = rowBase + warp * 32 + mf * 16 + tg;
            int col = colBase + nf * 8 + tk * 2;
            if (col < NC) {
                float b0 = 0.0f, b1 = 0.0f;
                if (MODE == 0) { b0 = g_bias[col]; b1 = g_bias[col + 1]; }
                if (row < Mrows) {
                    float2 v0 = make_float2(acc[mf][nf][0] + b0, acc[mf][nf][1] + b1);
                    *(float2*)(Cout + (size_t)row * NC + col) = v0;
                }
                if (row + 8 < Mrows) {
                    float2 v1 = make_float2(acc[mf][nf][2] + b0, acc[mf][nf][3] + b1);
                    *(float2*)(Cout + (size_t)(row + 8) * NC + col) = v1;
                }
            }
        }
    }
}

// ---------------------------------------------------------------------------
// Leaves (nodes 127..254): c = sig(i)*tanh(u); h = sig(o)*tanh(c)
// ---------------------------------------------------------------------------
__global__ void leaf_kernel()
{
    int idx = blockIdx.x * blockDim.x + threadIdx.x;
    if (idx >= 128 * B_ * HID) return;
    int n = idx % HID;
    int r = idx / HID;
    int row = 127 * B_ + r;
    const float* wx = g_wx + (size_t)row * NC;
    float iv = sigmoidf(wx[n]);
    float ov = sigmoidf(wx[300 + n]);
    float uv = tanhf(wx[600 + n]);
    float c = iv * uv;
    g_C[(size_t)row * HID + n] = c;
    g_H[(size_t)row * HID + n] = ov * tanhf(c);
}

// ---------------------------------------------------------------------------
// Per-level combine: parents p0..p0+np-1.
// ---------------------------------------------------------------------------
__global__ void level_pw(int p0, int np)
{
    int idx = blockIdx.x * blockDim.x + threadIdx.x;
    int tot = np * B_ * HID;
    if (idx >= tot) return;
    int n  = idx % HID;
    int r  = idx / HID;
    int b  = r % B_;
    int pi = r / B_;
    int p  = p0 + pi;

    const float* wx = g_wx + (size_t)(p * B_ + b) * NC;
    const float* Tl = g_T + (size_t)((2 * pi) * B_ + b) * NC;
    const float* Tr = g_T + (size_t)((2 * pi + 1) * B_ + b) * NC;

    float iv = sigmoidf(wx[n]       + Tl[n]       + Tr[n]);
    float ov = sigmoidf(wx[300 + n] + Tl[300 + n] + Tr[300 + n]);
    float uv = tanhf   (wx[600 + n] + Tl[600 + n] + Tr[600 + n]);
    float fl = sigmoidf(wx[900 + n] + Tl[900 + n]);
    float fr = sigmoidf(wx[900 + n] + Tr[900 + n]);

    int lc = 2 * p + 1, rc = 2 * p + 2;
    float fc = fl * g_C[(size_t)(lc * B_ + b) * HID + n]
             + fr * g_C[(size_t)(rc * B_ + b) * HID + n];
    float c = iv * uv + fc;
    float h = ov * tanhf(c);
    g_C[(size_t)(p * B_ + b) * HID + n] = c;
    g_H[(size_t)(p * B_ + b) * HID + n] = h;
}

// ---------------------------------------------------------------------------
// Output head: logits = H[root] @ W_out + b_out; log_softmax (2 classes).
// ---------------------------------------------------------------------------
__global__ __launch_bounds__(64) void out_kernel(
    const float* __restrict__ W_out, const float* __restrict__ b_out,
    float* __restrict__ out)
{
    const int b = threadIdx.x;
    const float* h = g_H + (size_t)b * HID;   // node 0 rows
    float l0 = b_out[0], l1 = b_out[1];
    #pragma unroll 4
    for (int k = 0; k < HID; ++k) {
        float hv = h[k];
        l0 = fmaf(hv, W_out[k * 2 + 0], l0);
        l1 = fmaf(hv, W_out[k * 2 + 1], l1);
    }
    float m   = fmaxf(l0, l1);
    float lse = m + logf(expf(l0 - m) + expf(l1 - m));
    out[b * 2 + 0] = l0 - lse;
    out[b * 2 + 1] = l1 - lse;
}

// ---------------------------------------------------------------------------
extern "C" void kernel_launch(void* const* d_in, const int* in_sizes, int n_in,
                              void* d_out, int out_size)
{
    (void)in_sizes; (void)n_in; (void)out_size;
    const int*   x     = (const int*)  d_in[0];
    const float* embed = (const float*)d_in[3];
    const float* W_iou = (const float*)d_in[4];
    const float* U_iou = (const float*)d_in[5];
    const float* b_iou = (const float*)d_in[6];
    const float* W_f   = (const float*)d_in[7];
    const float* U_f   = (const float*)d_in[8];
    const float* b_f   = (const float*)d_in[9];
    const float* W_out = (const float*)d_in[10];
    const float* b_out = (const float*)d_in[11];

    prep_kernel<<<(NBG * KCH_U * 32 + 255) / 256, 256>>>(W_iou, W_f, U_iou, U_f, b_iou, b_f);

    // wx = [emb@W_iou + b_iou | emb@W_f + b_f] for all 16320 rows
    gemm_tf32<0><<<dim3(128, 19), 128>>>(embed, x, 0, NROWS);

    leaf_kernel<<<(128 * B_ * HID + 255) / 256, 256>>>();

    for (int d = 6; d >= 0; --d) {
        int np = 1 << d;
        int p0 = np - 1;
        int c0 = 2 * np - 1;
        int nc = 2 * np;
        // T = H[children] @ [U_iou | U_f]
        gemm_tf32<1><<<dim3(nc / 2, 19), 128>>>(embed, x, c0, nc * B_);
        level_pw<<<(np * B_ * HID + 255) / 256, 256>>>(p0, np);
    }

    out_kernel<<<1, 64>>>(W_out, b_out, (float*)d_out);
}

// round 5
// speedup vs baseline: 1.8362x; 1.8362x over previous
#include <cuda_runtime.h>
#include <math.h>
#include <stdint.h>

#define SN    255
#define B_    64
#define EMB   200
#define HID   300
#define NROWS (SN * B_)     // 16320
#define NC    1200          // concat cols: [iou(900) | f(300)]
#define KCH_E 13            // ceil(200/16)
#define KCH_U 19            // ceil(300/16)
#define NBG2  160           // 10 N-blocks * 16 fragment groups (1280 padded cols)

// ---- device scratch (no allocation in kernel_launch) ----
__device__ float g_wx[NROWS * NC];
__device__ float g_H [NROWS * HID];
__device__ float g_C [NROWS * HID];
__device__ float g_T [8192 * NC];
// B matrices pre-packed in mma-fragment order (tf32):
// entry ((nbg*KCH + kch)*32 + lane) = { B[n][k+tk], B[n][k+tk+4], B[n][k+8+tk], B[n][k+12+tk] }
// n = nbg*8 + (lane>>2), tk = lane&3, k = kch*16.
__device__ uint4 g_Bw_f[NBG2 * KCH_E * 32];
__device__ uint4 g_Bu_f[NBG2 * KCH_U * 32];
__device__ float g_bias[NC];

__device__ __forceinline__ float sigmoidf(float x) { return 1.0f / (1.0f + expf(-x)); }
__device__ __forceinline__ uint32_t f2tf(float x) {
    uint32_t u; asm("cvt.rna.tf32.f32 %0, %1;" : "=r"(u) : "f"(x)); return u;
}

// ---------------------------------------------------------------------------
// Prep: pack tf32 B matrices into fragment order + concat bias.
// ---------------------------------------------------------------------------
__global__ void prep_kernel(const float* __restrict__ W_iou, const float* __restrict__ W_f,
                            const float* __restrict__ U_iou, const float* __restrict__ U_f,
                            const float* __restrict__ b_iou, const float* __restrict__ b_f)
{
    int idx = blockIdx.x * blockDim.x + threadIdx.x;

    if (idx < NBG2 * KCH_E * 32) {
        int lane = idx & 31;
        int kch  = (idx >> 5) % KCH_E;
        int nbg  = idx / (32 * KCH_E);
        int n  = nbg * 8 + (lane >> 2);
        int tk = lane & 3;
        int kb = kch * 16;
        uint4 v; uint32_t* vp = (uint32_t*)&v;
        #pragma unroll
        for (int q = 0; q < 4; ++q) {
            int k = kb + ((q & 1) ? 4 : 0) + ((q >> 1) ? 8 : 0) + tk;
            float f = 0.0f;
            if (k < EMB && n < NC)
                f = (n < 900) ? W_iou[k * 900 + n] : W_f[k * 300 + (n - 900)];
            vp[q] = f2tf(f);
        }
        g_Bw_f[idx] = v;
    }
    if (idx < NBG2 * KCH_U * 32) {
        int lane = idx & 31;
        int kch  = (idx >> 5) % KCH_U;
        int nbg  = idx / (32 * KCH_U);
        int n  = nbg * 8 + (lane >> 2);
        int tk = lane & 3;
        int kb = kch * 16;
        uint4 v; uint32_t* vp = (uint32_t*)&v;
        #pragma unroll
        for (int q = 0; q < 4; ++q) {
            int k = kb + ((q & 1) ? 4 : 0) + ((q >> 1) ? 8 : 0) + tk;
            float f = 0.0f;
            if (k < HID && n < NC)
                f = (n < 900) ? U_iou[k * 900 + n] : U_f[k * 300 + (n - 900)];
            vp[q] = f2tf(f);
        }
        g_Bu_f[idx] = v;
    }
    if (idx < NC) g_bias[idx] = (idx < 900) ? b_iou[idx] : b_f[idx - 900];
}

// Fragment pack order fix: q index meaning must match consumer. Consumer uses:
//   x=B[k+tk], y=B[k+tk+4]  (kb=0);  z=B[k+8+tk], w=B[k+8+tk+4]  (kb=1)
// The loop above produces q0=k+tk, q1=k+4+tk, q2=k+8+tk, q3=k+12+tk -> matches.

// ---------------------------------------------------------------------------
// tf32 GEMM, 2-stage cp.async pipeline.
// Block 128(M) x 128(N), BK=16, 256 threads = 8 warps (4M x 2N), warp 32x64.
// A: raw fp32 rows (HW truncates to tf32), row-major smem stride 20 (conflict-free).
// B: pre-packed tf32 fragments, cp.async 16B contiguous.
// MODE 0: A = embed[x[row]] (K=200) -> g_wx (+bias)
// MODE 1: A = g_H rows from node c0 (K=300) -> g_T
// ---------------------------------------------------------------------------
template<int MODE>
__global__ __launch_bounds__(256, 2) void gemm5(
    const float* __restrict__ embedTab, const int* __restrict__ xg,
    int c0, int Mrows)
{
    constexpr int KSRC = (MODE == 0) ? EMB : HID;
    constexpr int KCH  = (MODE == 0) ? KCH_E : KCH_U;

    __shared__ __align__(16) float As[2][128][20];   // 20KB
    __shared__ __align__(16) uint4 Bs[2][16][32];    // 16KB
    __shared__ const float* arows[128];

    const int tid     = threadIdx.x;
    const int rowBase = blockIdx.x * 128;
    const int colBase = blockIdx.y * 128;

    if (tid < 128) {
        int row = rowBase + tid;
        int rc  = (row < Mrows) ? row : (Mrows - 1);
        arows[tid] = (MODE == 0)
            ? embedTab + (size_t)xg[rc] * EMB
            : g_H + (size_t)(c0 * B_ + rc) * HID;
    }
    __syncthreads();

    const int lane = tid & 31, warp = tid >> 5;
    const int wm = (warp & 3) * 32;        // warp M offset
    const int wn = (warp >> 2) * 64;       // warp N offset (elements)
    const int nbW = (wn >> 3);             // warp N fragment-group offset (0 or 8)
    const int tg = lane >> 2, tk = lane & 3;
    const uint4* gB = (MODE == 0) ? g_Bw_f : g_Bu_f;
    const int nbgBase = colBase >> 3;

    // precomputed cp.async coordinates
    const int ar0 = tid >> 1;              // unused pattern; chunks computed inline

    float acc[2][8][4] = {};

#define ISSUE(STG, KCHV)                                                          \
    do {                                                                          \
        int _k0 = (KCHV) * 16;                                                    \
        _Pragma("unroll")                                                         \
        for (int _i = 0; _i < 2; ++_i) {                                          \
            int _e = tid + _i * 256;                                              \
            int _r = _e >> 2, _c = _e & 3;                                        \
            uint32_t _d = (uint32_t)__cvta_generic_to_shared(&As[STG][_r][_c*4]); \
            const float* _s = arows[_r] + _k0 + _c * 4;                           \
            int _vb = KSRC - (_k0 + _c * 4);                                      \
            int _sz = (_vb >= 4) ? 16 : ((_vb > 0) ? _vb * 4 : 0);                \
            asm volatile("cp.async.ca.shared.global [%0], [%1], 16, %2;"          \
                         :: "r"(_d), "l"(_s), "r"(_sz));                          \
        }                                                                         \
        _Pragma("unroll")                                                         \
        for (int _i = 0; _i < 2; ++_i) {                                          \
            int _e = tid + _i * 256;                                              \
            int _nb = _e >> 5, _ln = _e & 31;                                     \
            uint32_t _d = (uint32_t)__cvta_generic_to_shared(&Bs[STG][_nb][_ln]); \
            const uint4* _s = gB + ((size_t)(nbgBase + _nb) * KCH + (KCHV)) * 32 + _ln; \
            asm volatile("cp.async.ca.shared.global [%0], [%1], 16;"              \
                         :: "r"(_d), "l"(_s));                                    \
        }                                                                         \
        asm volatile("cp.async.commit_group;");                                   \
    } while (0)

    ISSUE(0, 0);

    for (int kch = 0; kch < KCH; ++kch) {
        const int s = kch & 1;
        if (kch + 1 < KCH) {
            ISSUE(s ^ 1, kch + 1);
            asm volatile("cp.async.wait_group 1;");
        } else {
            asm volatile("cp.async.wait_group 0;");
        }
        __syncthreads();

        // A fragments for both k-substeps (raw fp32; HW truncates to tf32)
        uint32_t a[2][2][4];   // [kb][mf][4]
        #pragma unroll
        for (int kb = 0; kb < 2; ++kb)
            #pragma unroll
            for (int mf = 0; mf < 2; ++mf) {
                int r = wm + mf * 16 + tg;
                a[kb][mf][0] = __float_as_uint(As[s][r    ][kb * 8 + tk]);
                a[kb][mf][1] = __float_as_uint(As[s][r + 8][kb * 8 + tk]);
                a[kb][mf][2] = __float_as_uint(As[s][r    ][kb * 8 + tk + 4]);
                a[kb][mf][3] = __float_as_uint(As[s][r + 8][kb * 8 + tk + 4]);
            }

        #pragma unroll
        for (int nf = 0; nf < 8; ++nf) {
            uint4 bq = Bs[s][nbW + nf][lane];
            #pragma unroll
            for (int mf = 0; mf < 2; ++mf) {
                asm("mma.sync.aligned.m16n8k8.row.col.f32.tf32.tf32.f32 "
                    "{%0,%1,%2,%3},{%4,%5,%6,%7},{%8,%9},{%0,%1,%2,%3};"
                    : "+f"(acc[mf][nf][0]), "+f"(acc[mf][nf][1]),
                      "+f"(acc[mf][nf][2]), "+f"(acc[mf][nf][3])
                    : "r"(a[0][mf][0]), "r"(a[0][mf][1]), "r"(a[0][mf][2]), "r"(a[0][mf][3]),
                      "r"(bq.x), "r"(bq.y));
                asm("mma.sync.aligned.m16n8k8.row.col.f32.tf32.tf32.f32 "
                    "{%0,%1,%2,%3},{%4,%5,%6,%7},{%8,%9},{%0,%1,%2,%3};"
                    : "+f"(acc[mf][nf][0]), "+f"(acc[mf][nf][1]),
                      "+f"(acc[mf][nf][2]), "+f"(acc[mf][nf][3])
                    : "r"(a[1][mf][0]), "r"(a[1][mf][1]), "r"(a[1][mf][2]), "r"(a[1][mf][3]),
                      "r"(bq.z), "r"(bq.w));
            }
        }
        __syncthreads();
    }
#undef ISSUE

    (void)ar0;
    float* Cout = (MODE == 0) ? g_wx : g_T;
    #pragma unroll
    for (int mf = 0; mf < 2; ++mf) {
        #pragma unroll
        for (int nf = 0; nf < 8; ++nf) {
            int row = rowBase + wm + mf * 16 + tg;
            int col = colBase + wn + nf * 8 + tk * 2;
            if (col < NC) {
                float b0 = 0.0f, b1 = 0.0f;
                if (MODE == 0) { b0 = g_bias[col]; b1 = g_bias[col + 1]; }
                if (row < Mrows)
                    *(float2*)(Cout + (size_t)row * NC + col) =
                        make_float2(acc[mf][nf][0] + b0, acc[mf][nf][1] + b1);
                if (row + 8 < Mrows)
                    *(float2*)(Cout + (size_t)(row + 8) * NC + col) =
                        make_float2(acc[mf][nf][2] + b0, acc[mf][nf][3] + b1);
            }
        }
    }
}

// ---------------------------------------------------------------------------
// Leaves (nodes 127..254)
// ---------------------------------------------------------------------------
__global__ void leaf_kernel()
{
    int idx = blockIdx.x * blockDim.x + threadIdx.x;
    if (idx >= 128 * B_ * HID) return;
    int n = idx % HID;
    int r = idx / HID;
    int row = 127 * B_ + r;
    const float* wx = g_wx + (size_t)row * NC;
    float iv = sigmoidf(wx[n]);
    float ov = sigmoidf(wx[300 + n]);
    float uv = tanhf(wx[600 + n]);
    float c = iv * uv;
    g_C[(size_t)row * HID + n] = c;
    g_H[(size_t)row * HID + n] = ov * tanhf(c);
}

// ---------------------------------------------------------------------------
// Per-level combine: parents p0..p0+np-1.
// ---------------------------------------------------------------------------
__global__ void level_pw(int p0, int np)
{
    int idx = blockIdx.x * blockDim.x + threadIdx.x;
    int tot = np * B_ * HID;
    if (idx >= tot) return;
    int n  = idx % HID;
    int r  = idx / HID;
    int b  = r % B_;
    int pi = r / B_;
    int p  = p0 + pi;

    const float* wx = g_wx + (size_t)(p * B_ + b) * NC;
    const float* Tl = g_T + (size_t)((2 * pi) * B_ + b) * NC;
    const float* Tr = g_T + (size_t)((2 * pi + 1) * B_ + b) * NC;

    float iv = sigmoidf(wx[n]       + Tl[n]       + Tr[n]);
    float ov = sigmoidf(wx[300 + n] + Tl[300 + n] + Tr[300 + n]);
    float uv = tanhf   (wx[600 + n] + Tl[600 + n] + Tr[600 + n]);
    float fl = sigmoidf(wx[900 + n] + Tl[900 + n]);
    float fr = sigmoidf(wx[900 + n] + Tr[900 + n]);

    int lc = 2 * p + 1, rc = 2 * p + 2;
    float fc = fl * g_C[(size_t)(lc * B_ + b) * HID + n]
             + fr * g_C[(size_t)(rc * B_ + b) * HID + n];
    float c = iv * uv + fc;
    float h = ov * tanhf(c);
    g_C[(size_t)(p * B_ + b) * HID + n] = c;
    g_H[(size_t)(p * B_ + b) * HID + n] = h;
}

// ---------------------------------------------------------------------------
// Output head
// ---------------------------------------------------------------------------
__global__ __launch_bounds__(64) void out_kernel(
    const float* __restrict__ W_out, const float* __restrict__ b_out,
    float* __restrict__ out)
{
    const int b = threadIdx.x;
    const float* h = g_H + (size_t)b * HID;
    float l0 = b_out[0], l1 = b_out[1];
    #pragma unroll 4
    for (int k = 0; k < HID; ++k) {
        float hv = h[k];
        l0 = fmaf(hv, W_out[k * 2 + 0], l0);
        l1 = fmaf(hv, W_out[k * 2 + 1], l1);
    }
    float m   = fmaxf(l0, l1);
    float lse = m + logf(expf(l0 - m) + expf(l1 - m));
    out[b * 2 + 0] = l0 - lse;
    out[b * 2 + 1] = l1 - lse;
}

// ---------------------------------------------------------------------------
extern "C" void kernel_launch(void* const* d_in, const int* in_sizes, int n_in,
                              void* d_out, int out_size)
{
    (void)in_sizes; (void)n_in; (void)out_size;
    const int*   x     = (const int*)  d_in[0];
    const float* embed = (const float*)d_in[3];
    const float* W_iou = (const float*)d_in[4];
    const float* U_iou = (const float*)d_in[5];
    const float* b_iou = (const float*)d_in[6];
    const float* W_f   = (const float*)d_in[7];
    const float* U_f   = (const float*)d_in[8];
    const float* b_f   = (const float*)d_in[9];
    const float* W_out = (const float*)d_in[10];
    const float* b_out = (const float*)d_in[11];

    prep_kernel<<<(NBG2 * KCH_U * 32 + 255) / 256, 256>>>(W_iou, W_f, U_iou, U_f, b_iou, b_f);

    // wx = [emb@W_iou + b_iou | emb@W_f + b_f] for all 16320 rows
    gemm5<0><<<dim3(128, 10), 256>>>(embed, x, 0, NROWS);

    leaf_kernel<<<(128 * B_ * HID + 255) / 256, 256>>>();

    for (int d = 6; d >= 0; --d) {
        int np = 1 << d;
        int p0 = np - 1;
        int c0 = 2 * np - 1;
        int nc = 2 * np;
        // T = H[children] @ [U_iou | U_f]
        gemm5<1><<<dim3(nc / 2, 10), 256>>>(embed, x, c0, nc * B_);
        level_pw<<<(np * B_ * HID + 255) / 256, 256>>>(p0, np);
    }

    out_kernel<<<1, 64>>>(W_out, b_out, (float*)d_out);
}